// round 13
// baseline (speedup 1.0000x reference)
#include <cuda_runtime.h>
#include <cuda_fp16.h>
#include <cstdint>

// ---------------------------------------------------------------------------
// Problem constants
// ---------------------------------------------------------------------------
#define T_DIM 512
#define H_DIM 4096
#define I_DIM 11008

#define NK1 (H_DIM / 64)         // 64 k-stages for gemm1 (BK=64)
#define NK2 (I_DIM / 64)         // 172 k-stages for gemm2 (BK=64)

// gemm1: tile M=128, N=64 (per matrix), BK=64. pitch 144 = 9x16B
#define G1_PITCH 144
#define G1_A_BYTES (128 * G1_PITCH)          // 18432 : A [128 t][64 k halfs]
#define G1_B_BYTES (64 * G1_PITCH)           // 9216  : Bg/Bu [64 i][64 k halfs]
#define G1_STAGE (G1_A_BYTES + 2 * G1_B_BYTES)   // 36864
#define G1_SMEM (2 * G1_STAGE)                   // 73728 (dynamic)

// gemm2: tile M=128, N=64, BK=64. pitch 144
#define G2_PITCH 144
#define G2_A_BYTES (128 * G2_PITCH)     // 18432
#define G2_B_BYTES (64 * G2_PITCH)      // 9216
#define G2_STAGE (G2_A_BYTES + G2_B_BYTES)  // 27648
#define G2_SMEM (2 * G2_STAGE)              // 55296 (dynamic)

// Scratch (device globals — allocations are forbidden)
__device__ __align__(256) __half g_h[(size_t)T_DIM * I_DIM];   // 11.3 MB
__device__ __align__(256) __half g_x[(size_t)T_DIM * H_DIM];   // 4 MB

// ---------------------------------------------------------------------------
// sm_80-baseline PTX helpers (NO tcgen05 — harness targets compute_103 non-'a')
// ---------------------------------------------------------------------------
__device__ __forceinline__ uint32_t smem_u32(const void* p) {
    uint32_t a;
    asm("{ .reg .u64 t; cvta.to.shared.u64 t, %1; cvt.u32.u64 %0, t; }"
        : "=r"(a) : "l"(p));
    return a;
}

__device__ __forceinline__ void ldsm_x4(uint32_t* r, uint32_t addr) {
    asm volatile("ldmatrix.sync.aligned.m8n8.x4.shared.b16 {%0,%1,%2,%3}, [%4];"
                 : "=r"(r[0]), "=r"(r[1]), "=r"(r[2]), "=r"(r[3]) : "r"(addr));
}

__device__ __forceinline__ void ldsm_x4_t(uint32_t* r, uint32_t addr) {
    asm volatile("ldmatrix.sync.aligned.m8n8.x4.trans.shared.b16 {%0,%1,%2,%3}, [%4];"
                 : "=r"(r[0]), "=r"(r[1]), "=r"(r[2]), "=r"(r[3]) : "r"(addr));
}

__device__ __forceinline__ void mma16816(float* c, const uint32_t* a, const uint32_t* b) {
    asm volatile(
        "mma.sync.aligned.m16n8k16.row.col.f32.f16.f16.f32 "
        "{%0,%1,%2,%3}, {%4,%5,%6,%7}, {%8,%9}, {%0,%1,%2,%3};"
        : "+f"(c[0]), "+f"(c[1]), "+f"(c[2]), "+f"(c[3])
        : "r"(a[0]), "r"(a[1]), "r"(a[2]), "r"(a[3]), "r"(b[0]), "r"(b[1]));
}

__device__ __forceinline__ void cp16(uint32_t sdst, const void* gsrc) {
    asm volatile("cp.async.cg.shared.global [%0], [%1], 16;"
                 :: "r"(sdst), "l"(__cvta_generic_to_global(gsrc)));
}
#define CP_COMMIT() asm volatile("cp.async.commit_group;")
#define CP_WAIT0()  asm volatile("cp.async.wait_group 0;")

// ---------------------------------------------------------------------------
// Kernel 0: x fp32 -> g_x fp16 (tiny streaming convert)
// ---------------------------------------------------------------------------
__global__ __launch_bounds__(256) void cvt_x_kernel(const float* __restrict__ x) {
    size_t i = (size_t)blockIdx.x * 256 + threadIdx.x;   // float4 index
    float4 v = reinterpret_cast<const float4*>(x)[i];
    __half2 h0 = __floats2half2_rn(v.x, v.y);
    __half2 h1 = __floats2half2_rn(v.z, v.w);
    uint2 w;
    w.x = *(uint32_t*)&h0; w.y = *(uint32_t*)&h1;
    reinterpret_cast<uint2*>(g_x)[i] = w;
}

// ---------------------------------------------------------------------------
// GEMM1 staging (BK=64); B staged in two half-batches (rows 0-31 / 32-63)
// ---------------------------------------------------------------------------
__device__ __forceinline__ void cp_a_g1(uint32_t sA, int t0, int k0, int tid) {
#pragma unroll
    for (int j = 0; j < 4; j++) {            // 128 rows x 8 chunks (16B)
        int idx = tid + j * 256;
        int r = idx >> 3, c = idx & 7;
        cp16(sA + r * G1_PITCH + c * 16, g_x + (size_t)(t0 + r) * H_DIM + k0 + c * 8);
    }
    CP_COMMIT();
}

__device__ __forceinline__ void ldg_b_g1_half(const float* __restrict__ wg,
                                              const float* __restrict__ wu,
                                              int i0, int k0, int tid, int half,
                                              float4* bgv, float4* buv) {
#pragma unroll
    for (int j = 0; j < 2; j++) {            // 32 rows x 16 float4
        int idx = tid + (half * 2 + j) * 256;
        int r = idx >> 4, c = idx & 15;
        bgv[j] = *(const float4*)(wg + (size_t)(i0 + r) * H_DIM + k0 + c * 4);
        buv[j] = *(const float4*)(wu + (size_t)(i0 + r) * H_DIM + k0 + c * 4);
    }
}

__device__ __forceinline__ void sts_b_g1_half(char* st, int tid, int half,
                                              float sgv, float suv,
                                              const float4* bgv, const float4* buv) {
#pragma unroll
    for (int j = 0; j < 2; j++) {
        int idx = tid + (half * 2 + j) * 256;
        int r = idx >> 4, c = idx & 15;
        {
            __half2 h0 = __floats2half2_rn(bgv[j].x * sgv, bgv[j].y * sgv);
            __half2 h1 = __floats2half2_rn(bgv[j].z * sgv, bgv[j].w * sgv);
            uint2 w;
            w.x = *(uint32_t*)&h0; w.y = *(uint32_t*)&h1;
            *(uint2*)(st + G1_A_BYTES + r * G1_PITCH + c * 8) = w;
        }
        {
            __half2 h0 = __floats2half2_rn(buv[j].x * suv, buv[j].y * suv);
            __half2 h1 = __floats2half2_rn(buv[j].z * suv, buv[j].w * suv);
            uint2 w;
            w.x = *(uint32_t*)&h0; w.y = *(uint32_t*)&h1;
            *(uint2*)(st + G1_A_BYTES + G1_B_BYTES + r * G1_PITCH + c * 8) = w;
        }
    }
}

// ---------------------------------------------------------------------------
// Kernel 1: gate/up dual GEMM + SwiGLU -> g_h (fp16)
//   CTA: M=128, N=64 (per matrix), BK=64. 8 warps = 2(M) x 2(N) x 2(K-split).
//   Warp tile 64x32 per matrix, half of the BK slab. K-partials reduced via
//   smem at the epilogue (ws=1 -> ws=0), then silu.
// ---------------------------------------------------------------------------
__global__ __launch_bounds__(256, 1) void gemm1_kernel(
    const float* __restrict__ wg, const float* __restrict__ wu,
    const float* __restrict__ sg, const float* __restrict__ su) {
    extern __shared__ __align__(128) char sm[];
    const int tid = threadIdx.x, wid = tid >> 5, l = tid & 31;
    const int ws = wid >> 2;                 // k-split half
    const int wm = (wid >> 1) & 1;           // 64-row block
    const int wn = wid & 1;                  // 32-col block
    const int t0 = blockIdx.x * 128, i0 = blockIdx.y * 64;
    const int iblk = i0 >> 7;
    const uint32_t sbase = smem_u32(sm);

    float cg[4][4][4], cu[4][4][4];
#pragma unroll
    for (int a = 0; a < 4; a++)
#pragma unroll
        for (int b = 0; b < 4; b++)
#pragma unroll
            for (int d = 0; d < 4; d++) { cg[a][b][d] = 0.f; cu[a][b][d] = 0.f; }

    float4 bgv[2], buv[2];
    {
        float s0g = __ldg(sg + iblk * 32), s0u = __ldg(su + iblk * 32);
        cp_a_g1(sbase, t0, 0, tid);
        ldg_b_g1_half(wg, wu, i0, 0, tid, 0, bgv, buv);
        sts_b_g1_half(sm, tid, 0, s0g, s0u, bgv, buv);
        ldg_b_g1_half(wg, wu, i0, 0, tid, 1, bgv, buv);
        sts_b_g1_half(sm, tid, 1, s0g, s0u, bgv, buv);
        CP_WAIT0();
    }
    __syncthreads();

    const int kh = ws * 32;
    for (int it = 0; it < NK1; it++) {
        const bool pre = (it + 1 < NK1);
        float sgv = 0.f, suv = 0.f;
        if (pre) {
            cp_a_g1(sbase + ((it + 1) & 1) * G1_STAGE, t0, (it + 1) * 64, tid);
            ldg_b_g1_half(wg, wu, i0, (it + 1) * 64, tid, 0, bgv, buv);
            int kb = (it + 1) >> 1;
            sgv = __ldg(sg + iblk * 32 + kb);
            suv = __ldg(su + iblk * 32 + kb);
        }

        const uint32_t sA = sbase + (it & 1) * G1_STAGE;
        const uint32_t sBg = sA + G1_A_BYTES;
        const uint32_t sBu = sBg + G1_B_BYTES;
        char* stn = sm + ((it + 1) & 1) * G1_STAGE;

#pragma unroll
        for (int kx = 0; kx < 2; kx++) {
            const int kk = kh + kx * 16;
            // B frags: n32 for both matrices
            uint32_t bg[4][2], bu[4][2];
#pragma unroll
            for (int p = 0; p < 2; p++) {
                int m = l >> 3;
                int row = wn * 32 + (p * 2 + (m >> 1)) * 8 + (l & 7);
                uint32_t aoff = row * G1_PITCH + (kk + (m & 1) * 8) * 2;
                uint32_t r4[4];
                ldsm_x4(r4, sBg + aoff);
                bg[p * 2][0] = r4[0]; bg[p * 2][1] = r4[1];
                bg[p * 2 + 1][0] = r4[2]; bg[p * 2 + 1][1] = r4[3];
                ldsm_x4(r4, sBu + aoff);
                bu[p * 2][0] = r4[0]; bu[p * 2][1] = r4[1];
                bu[p * 2 + 1][0] = r4[2]; bu[p * 2 + 1][1] = r4[3];
            }
            // A frags + mma, in mi-pairs (keeps a2 at 8 regs)
#pragma unroll
            for (int hlf = 0; hlf < 2; hlf++) {
                uint32_t a2[2][4];
#pragma unroll
                for (int mj = 0; mj < 2; mj++) {
                    int mi = hlf * 2 + mj;
                    ldsm_x4(a2[mj], sA + (wm * 64 + mi * 16 + (l & 15)) * G1_PITCH +
                                       (kk + ((l >> 4) << 3)) * 2);
                }
#pragma unroll
                for (int mj = 0; mj < 2; mj++)
#pragma unroll
                    for (int n = 0; n < 4; n++) {
                        mma16816(cg[hlf * 2 + mj][n], a2[mj], bg[n]);
                        mma16816(cu[hlf * 2 + mj][n], a2[mj], bu[n]);
                    }
            }
            // interleave staging between the two kk slabs
            if (kx == 0 && pre) {
                sts_b_g1_half(stn, tid, 0, sgv, suv, bgv, buv);
                ldg_b_g1_half(wg, wu, i0, (it + 1) * 64, tid, 1, bgv, buv);
            }
        }

        if (pre) {
            sts_b_g1_half(stn, tid, 1, sgv, suv, bgv, buv);
            CP_WAIT0();
        }
        __syncthreads();
    }

    // ---- K-split reduction via smem, then SwiGLU epilogue (ws==0 warps) ----
    const int pid = wid & 3;                 // (wm, wn) pair id
    if (ws == 1) {
#pragma unroll
        for (int mi = 0; mi < 4; mi++)
#pragma unroll
            for (int n = 0; n < 4; n++) {
                int c = mi * 4 + n;
                *(float4*)(sm + pid * 16384 + c * 512 + l * 16) =
                    make_float4(cg[mi][n][0], cg[mi][n][1], cg[mi][n][2], cg[mi][n][3]);
                *(float4*)(sm + pid * 16384 + 8192 + c * 512 + l * 16) =
                    make_float4(cu[mi][n][0], cu[mi][n][1], cu[mi][n][2], cu[mi][n][3]);
            }
    }
    __syncthreads();
    if (ws == 0) {
#pragma unroll
        for (int mi = 0; mi < 4; mi++)
#pragma unroll
            for (int n = 0; n < 4; n++) {
                int c = mi * 4 + n;
                float4 vg = *(float4*)(sm + pid * 16384 + c * 512 + l * 16);
                float4 vu = *(float4*)(sm + pid * 16384 + 8192 + c * 512 + l * 16);
                cg[mi][n][0] += vg.x; cg[mi][n][1] += vg.y;
                cg[mi][n][2] += vg.z; cg[mi][n][3] += vg.w;
                cu[mi][n][0] += vu.x; cu[mi][n][1] += vu.y;
                cu[mi][n][2] += vu.z; cu[mi][n][3] += vu.w;
            }
#pragma unroll
        for (int mi = 0; mi < 4; mi++)
#pragma unroll
            for (int n = 0; n < 4; n++) {
                int row = t0 + wm * 64 + mi * 16 + (l >> 2);
                int col = i0 + wn * 32 + n * 8 + ((l & 3) << 1);
                {
                    float g0 = cg[mi][n][0], g1 = cg[mi][n][1];
                    float h0 = g0 * cu[mi][n][0] / (1.0f + __expf(-g0));
                    float h1 = g1 * cu[mi][n][1] / (1.0f + __expf(-g1));
                    __half2 hv = __floats2half2_rn(h0, h1);
                    *(uint32_t*)(&g_h[(size_t)row * I_DIM + col]) = *(uint32_t*)&hv;
                }
                {
                    float g0 = cg[mi][n][2], g1 = cg[mi][n][3];
                    float h0 = g0 * cu[mi][n][2] / (1.0f + __expf(-g0));
                    float h1 = g1 * cu[mi][n][3] / (1.0f + __expf(-g1));
                    __half2 hv = __floats2half2_rn(h0, h1);
                    *(uint32_t*)(&g_h[(size_t)(row + 8) * I_DIM + col]) = *(uint32_t*)&hv;
                }
            }
    }
}

// ---------------------------------------------------------------------------
// GEMM2 staging (tile 128x64, BK=64) — unchanged from R11
// ---------------------------------------------------------------------------
__device__ __forceinline__ void cp_a_g2(uint32_t sA, int t0, int k0, int tid) {
#pragma unroll
    for (int j = 0; j < 4; j++) {
        int idx = tid + j * 256;
        int r = idx >> 3, c = idx & 7;
        cp16(sA + r * G2_PITCH + c * 16, g_h + (size_t)(t0 + r) * I_DIM + k0 + c * 8);
    }
    CP_COMMIT();
}

__device__ __forceinline__ void ldg_b_g2(const float* __restrict__ wd,
                                         int h0, int k0, int tid, float4* b4) {
#pragma unroll
    for (int j = 0; j < 4; j++) {
        int idx = tid + j * 256;
        int r = idx >> 4, c4 = idx & 15;
        b4[j] = *(const float4*)(wd + (size_t)(k0 + r) * H_DIM + h0 + c4 * 4);
    }
}

__device__ __forceinline__ void sts_b_g2(char* st, int tid, float s, const float4* b4) {
#pragma unroll
    for (int j = 0; j < 4; j++) {
        int idx = tid + j * 256;
        int r = idx >> 4, c4 = idx & 15;
        __half2 h0 = __floats2half2_rn(b4[j].x * s, b4[j].y * s);
        __half2 h1 = __floats2half2_rn(b4[j].z * s, b4[j].w * s);
        uint2 w;
        w.x = *(uint32_t*)&h0; w.y = *(uint32_t*)&h1;
        *(uint2*)(st + G2_A_BYTES + r * G2_PITCH + c4 * 8) = w;
    }
}

__global__ __launch_bounds__(256, 2) void gemm2_kernel(
    const float* __restrict__ wd, const float* __restrict__ sd,
    float* __restrict__ out) {
    extern __shared__ __align__(128) char sm2[];
    const int tid = threadIdx.x, wid = tid >> 5, l = tid & 31;
    const int wm = wid & 3, wn = wid >> 2;
    const int t0 = blockIdx.x * 128, h0 = blockIdx.y * 64;
    const int hb = h0 >> 7;
    const uint32_t sbase = smem_u32(sm2);

    float c[2][4][4];
#pragma unroll
    for (int a = 0; a < 2; a++)
#pragma unroll
        for (int b = 0; b < 4; b++)
#pragma unroll
            for (int d = 0; d < 4; d++) c[a][b][d] = 0.f;

    float4 b4[4];
    cp_a_g2(sbase, t0, 0, tid);
    ldg_b_g2(wd, h0, 0, tid, b4);
    sts_b_g2(sm2, tid, __ldg(sd + hb), b4);
    CP_WAIT0();
    __syncthreads();

    for (int it = 0; it < NK2; it++) {
        float sv = 0.f;
        if (it + 1 < NK2) {
            cp_a_g2(sbase + ((it + 1) & 1) * G2_STAGE, t0, (it + 1) * 64, tid);
            ldg_b_g2(wd, h0, (it + 1) * 64, tid, b4);
            sv = __ldg(sd + ((it + 1) >> 1) * (H_DIM / 128) + hb);
        }

        const uint32_t sA = sbase + (it & 1) * G2_STAGE;
        const uint32_t sB = sA + G2_A_BYTES;
#pragma unroll
        for (int kk = 0; kk < 64; kk += 16) {
            uint32_t a2[2][4];
#pragma unroll
            for (int mi = 0; mi < 2; mi++)
                ldsm_x4(a2[mi], sA + (wm * 32 + mi * 16 + (l & 15)) * G2_PITCH +
                                   (kk + ((l >> 4) << 3)) * 2);
            uint32_t bf[4][2];
#pragma unroll
            for (int p = 0; p < 2; p++) {
                int t = l >> 3, rr = l & 7;
                uint32_t baddr = sB + (kk + (t & 1) * 8 + rr) * G2_PITCH +
                                 (wn * 32 + p * 16 + (t >> 1) * 8) * 2;
                uint32_t r4[4];
                ldsm_x4_t(r4, baddr);
                bf[p * 2][0] = r4[0]; bf[p * 2][1] = r4[1];
                bf[p * 2 + 1][0] = r4[2]; bf[p * 2 + 1][1] = r4[3];
            }
#pragma unroll
            for (int mi = 0; mi < 2; mi++)
#pragma unroll
                for (int n = 0; n < 4; n++)
                    mma16816(c[mi][n], a2[mi], bf[n]);
        }

        if (it + 1 < NK2) {
            sts_b_g2(sm2 + ((it + 1) & 1) * G2_STAGE, tid, sv, b4);
            CP_WAIT0();
        }
        __syncthreads();
    }

#pragma unroll
    for (int mi = 0; mi < 2; mi++)
#pragma unroll
        for (int n = 0; n < 4; n++) {
            int row = t0 + wm * 32 + mi * 16 + (l >> 2);
            int col = h0 + wn * 32 + n * 8 + ((l & 3) << 1);
            float2 v0 = make_float2(c[mi][n][0], c[mi][n][1]);
            float2 v1 = make_float2(c[mi][n][2], c[mi][n][3]);
            *(float2*)(out + (size_t)row * H_DIM + col) = v0;
            *(float2*)(out + (size_t)(row + 8) * H_DIM + col) = v1;
        }
}

// ---------------------------------------------------------------------------
// Launch
// ---------------------------------------------------------------------------
extern "C" void kernel_launch(void* const* d_in, const int* in_sizes, int n_in,
                              void* d_out, int out_size) {
    const float* x  = (const float*)d_in[0];
    const float* wg = (const float*)d_in[1];
    const float* wu = (const float*)d_in[2];
    const float* wd = (const float*)d_in[3];
    const float* sg = (const float*)d_in[4];
    const float* su = (const float*)d_in[5];
    const float* sd = (const float*)d_in[6];
    float* out = (float*)d_out;
    (void)in_sizes; (void)n_in; (void)out_size;

    cudaFuncSetAttribute(gemm1_kernel, cudaFuncAttributeMaxDynamicSharedMemorySize,
                         G1_SMEM);
    cudaFuncSetAttribute(gemm2_kernel, cudaFuncAttributeMaxDynamicSharedMemorySize,
                         G2_SMEM);

    cvt_x_kernel<<<(T_DIM * H_DIM / 4) / 256, 256>>>(x);
    // T-tiles fastest (blockIdx.x) so concurrent CTAs dedup weight reads in L2
    gemm1_kernel<<<dim3(T_DIM / 128, I_DIM / 64), 256, G1_SMEM>>>(wg, wu, sg, su);
    gemm2_kernel<<<dim3(T_DIM / 128, H_DIM / 64), 256, G2_SMEM>>>(wd, sd, out);
}

// round 15
// speedup vs baseline: 1.9168x; 1.9168x over previous
#include <cuda_runtime.h>
#include <cuda_fp16.h>
#include <cstdint>

// ---------------------------------------------------------------------------
// Problem constants
// ---------------------------------------------------------------------------
#define T_DIM 512
#define H_DIM 4096
#define I_DIM 11008

#define NK1 (H_DIM / 64)         // 64 k-stages for gemm1 (BK=64)
#define NK2 (I_DIM / 64)         // 172 k-stages for gemm2 (BK=64)

// gemm1: tile M=128, N=64 (per matrix), BK=64. pitch 144 = 9x16B
#define G1_PITCH 144
#define G1_A_BYTES (128 * G1_PITCH)          // 18432 : A [128 t][64 k halfs]
#define G1_B_BYTES (64 * G1_PITCH)           // 9216  : Bg/Bu [64 i][64 k halfs]
#define G1_STAGE (G1_A_BYTES + 2 * G1_B_BYTES)   // 36864
#define G1_SMEM (2 * G1_STAGE)                   // 73728 (dynamic)

// gemm2: tile M=128, N=64, BK=64. pitch 144
#define G2_PITCH 144
#define G2_A_BYTES (128 * G2_PITCH)     // 18432
#define G2_B_BYTES (64 * G2_PITCH)      // 9216
#define G2_STAGE (G2_A_BYTES + G2_B_BYTES)  // 27648
#define G2_SMEM (2 * G2_STAGE)              // 55296 (dynamic)

// Scratch (device globals — allocations are forbidden)
__device__ __align__(256) __half g_h[(size_t)T_DIM * I_DIM];   // 11.3 MB
__device__ __align__(256) __half g_x[(size_t)T_DIM * H_DIM];   // 4 MB

// ---------------------------------------------------------------------------
// sm_80-baseline PTX helpers (NO tcgen05 — harness targets compute_103 non-'a')
// ---------------------------------------------------------------------------
__device__ __forceinline__ uint32_t smem_u32(const void* p) {
    uint32_t a;
    asm("{ .reg .u64 t; cvta.to.shared.u64 t, %1; cvt.u32.u64 %0, t; }"
        : "=r"(a) : "l"(p));
    return a;
}

__device__ __forceinline__ void ldsm_x4(uint32_t* r, uint32_t addr) {
    asm volatile("ldmatrix.sync.aligned.m8n8.x4.shared.b16 {%0,%1,%2,%3}, [%4];"
                 : "=r"(r[0]), "=r"(r[1]), "=r"(r[2]), "=r"(r[3]) : "r"(addr));
}

__device__ __forceinline__ void ldsm_x4_t(uint32_t* r, uint32_t addr) {
    asm volatile("ldmatrix.sync.aligned.m8n8.x4.trans.shared.b16 {%0,%1,%2,%3}, [%4];"
                 : "=r"(r[0]), "=r"(r[1]), "=r"(r[2]), "=r"(r[3]) : "r"(addr));
}

__device__ __forceinline__ void mma16816(float* c, const uint32_t* a, const uint32_t* b) {
    asm volatile(
        "mma.sync.aligned.m16n8k16.row.col.f32.f16.f16.f32 "
        "{%0,%1,%2,%3}, {%4,%5,%6,%7}, {%8,%9}, {%0,%1,%2,%3};"
        : "+f"(c[0]), "+f"(c[1]), "+f"(c[2]), "+f"(c[3])
        : "r"(a[0]), "r"(a[1]), "r"(a[2]), "r"(a[3]), "r"(b[0]), "r"(b[1]));
}

__device__ __forceinline__ void cp16(uint32_t sdst, const void* gsrc) {
    asm volatile("cp.async.cg.shared.global [%0], [%1], 16;"
                 :: "r"(sdst), "l"(__cvta_generic_to_global(gsrc)));
}
#define CP_COMMIT() asm volatile("cp.async.commit_group;")
#define CP_WAIT0()  asm volatile("cp.async.wait_group 0;")

// ---------------------------------------------------------------------------
// Kernel 0: x fp32 -> g_x fp16 (tiny streaming convert)
// ---------------------------------------------------------------------------
__global__ __launch_bounds__(256) void cvt_x_kernel(const float* __restrict__ x) {
    size_t i = (size_t)blockIdx.x * 256 + threadIdx.x;   // float4 index
    float4 v = reinterpret_cast<const float4*>(x)[i];
    __half2 h0 = __floats2half2_rn(v.x, v.y);
    __half2 h1 = __floats2half2_rn(v.z, v.w);
    uint2 w;
    w.x = *(uint32_t*)&h0; w.y = *(uint32_t*)&h1;
    reinterpret_cast<uint2*>(g_x)[i] = w;
}

// ---------------------------------------------------------------------------
// GEMM1 staging (BK=64); B staged in two 32-row half-batches (16 regs live)
// ---------------------------------------------------------------------------
__device__ __forceinline__ void cp_a_g1(uint32_t sA, int t0, int k0, int tid) {
#pragma unroll
    for (int j = 0; j < 4; j++) {            // 128 rows x 8 chunks (16B)
        int idx = tid + j * 256;
        int r = idx >> 3, c = idx & 7;
        cp16(sA + r * G1_PITCH + c * 16, g_x + (size_t)(t0 + r) * H_DIM + k0 + c * 8);
    }
    CP_COMMIT();
}

__device__ __forceinline__ void ldg_b_g1_half(const float* __restrict__ wg,
                                              const float* __restrict__ wu,
                                              int i0, int k0, int tid, int half,
                                              float4* bgv, float4* buv) {
#pragma unroll
    for (int j = 0; j < 2; j++) {            // 32 rows x 16 float4
        int idx = tid + (half * 2 + j) * 256;
        int r = idx >> 4, c = idx & 15;
        bgv[j] = *(const float4*)(wg + (size_t)(i0 + r) * H_DIM + k0 + c * 4);
        buv[j] = *(const float4*)(wu + (size_t)(i0 + r) * H_DIM + k0 + c * 4);
    }
}

__device__ __forceinline__ void sts_b_g1_half(char* st, int tid, int half,
                                              float sgv, float suv,
                                              const float4* bgv, const float4* buv) {
#pragma unroll
    for (int j = 0; j < 2; j++) {
        int idx = tid + (half * 2 + j) * 256;
        int r = idx >> 4, c = idx & 15;
        {
            __half2 h0 = __floats2half2_rn(bgv[j].x * sgv, bgv[j].y * sgv);
            __half2 h1 = __floats2half2_rn(bgv[j].z * sgv, bgv[j].w * sgv);
            uint2 w;
            w.x = *(uint32_t*)&h0; w.y = *(uint32_t*)&h1;
            *(uint2*)(st + G1_A_BYTES + r * G1_PITCH + c * 8) = w;
        }
        {
            __half2 h0 = __floats2half2_rn(buv[j].x * suv, buv[j].y * suv);
            __half2 h1 = __floats2half2_rn(buv[j].z * suv, buv[j].w * suv);
            uint2 w;
            w.x = *(uint32_t*)&h0; w.y = *(uint32_t*)&h1;
            *(uint2*)(st + G1_A_BYTES + G1_B_BYTES + r * G1_PITCH + c * 8) = w;
        }
    }
}

// ---------------------------------------------------------------------------
// Kernel 1: gate/up dual GEMM + SwiGLU -> g_h (fp16)
//   CTA: M=128 (T), N=64 (I) per matrix, BK=64. 8 warps = 4(M) x 2(N).
//   Warp tile 32x32 per matrix (R11 geometry). A via cp.async from g_x;
//   B via reg-buffered LDG (two half-batches) + fused dequant-cvt.
// ---------------------------------------------------------------------------
__global__ __launch_bounds__(256, 2) void gemm1_kernel(
    const float* __restrict__ wg, const float* __restrict__ wu,
    const float* __restrict__ sg, const float* __restrict__ su) {
    extern __shared__ __align__(128) char sm[];
    const int tid = threadIdx.x, wid = tid >> 5, l = tid & 31;
    const int wm = wid & 3, wn = wid >> 2;
    const int t0 = blockIdx.x * 128, i0 = blockIdx.y * 64;
    const int iblk = i0 >> 7;
    const uint32_t sbase = smem_u32(sm);

    float cg[2][4][4], cu[2][4][4];
#pragma unroll
    for (int a = 0; a < 2; a++)
#pragma unroll
        for (int b = 0; b < 4; b++)
#pragma unroll
            for (int d = 0; d < 4; d++) { cg[a][b][d] = 0.f; cu[a][b][d] = 0.f; }

    float4 bgv[2], buv[2];
    {
        float s0g = __ldg(sg + iblk * 32), s0u = __ldg(su + iblk * 32);
        cp_a_g1(sbase, t0, 0, tid);
        ldg_b_g1_half(wg, wu, i0, 0, tid, 0, bgv, buv);
        sts_b_g1_half(sm, tid, 0, s0g, s0u, bgv, buv);
        ldg_b_g1_half(wg, wu, i0, 0, tid, 1, bgv, buv);
        sts_b_g1_half(sm, tid, 1, s0g, s0u, bgv, buv);
        CP_WAIT0();
    }
    __syncthreads();

    for (int it = 0; it < NK1; it++) {
        const bool pre = (it + 1 < NK1);
        float sgv = 0.f, suv = 0.f;
        if (pre) {
            cp_a_g1(sbase + ((it + 1) & 1) * G1_STAGE, t0, (it + 1) * 64, tid);
            ldg_b_g1_half(wg, wu, i0, (it + 1) * 64, tid, 0, bgv, buv);
            int kb = (it + 1) >> 1;
            sgv = __ldg(sg + iblk * 32 + kb);
            suv = __ldg(su + iblk * 32 + kb);
        }

        const uint32_t sA = sbase + (it & 1) * G1_STAGE;
        const uint32_t sBg = sA + G1_A_BYTES;
        const uint32_t sBu = sBg + G1_B_BYTES;
        char* stn = sm + ((it + 1) & 1) * G1_STAGE;

#pragma unroll
        for (int kx = 0; kx < 4; kx++) {
            const int kk = kx * 16;
            uint32_t a2[2][4];
#pragma unroll
            for (int mi = 0; mi < 2; mi++)
                ldsm_x4(a2[mi], sA + (wm * 32 + mi * 16 + (l & 15)) * G1_PITCH +
                                   (kk + ((l >> 4) << 3)) * 2);
            uint32_t bg[4][2], bu[4][2];
#pragma unroll
            for (int p = 0; p < 2; p++) {
                int m = l >> 3;
                int row = wn * 32 + (p * 2 + (m >> 1)) * 8 + (l & 7);
                uint32_t aoff = row * G1_PITCH + (kk + (m & 1) * 8) * 2;
                uint32_t r4[4];
                ldsm_x4(r4, sBg + aoff);
                bg[p * 2][0] = r4[0]; bg[p * 2][1] = r4[1];
                bg[p * 2 + 1][0] = r4[2]; bg[p * 2 + 1][1] = r4[3];
                ldsm_x4(r4, sBu + aoff);
                bu[p * 2][0] = r4[0]; bu[p * 2][1] = r4[1];
                bu[p * 2 + 1][0] = r4[2]; bu[p * 2 + 1][1] = r4[3];
            }
#pragma unroll
            for (int mi = 0; mi < 2; mi++)
#pragma unroll
                for (int n = 0; n < 4; n++) {
                    mma16816(cg[mi][n], a2[mi], bg[n]);
                    mma16816(cu[mi][n], a2[mi], bu[n]);
                }
            // After slab 1: store half-0 of next B, fetch half-1 (frees regs,
            // keeps only 16 staging regs live across the mma sections).
            if (kx == 1 && pre) {
                sts_b_g1_half(stn, tid, 0, sgv, suv, bgv, buv);
                ldg_b_g1_half(wg, wu, i0, (it + 1) * 64, tid, 1, bgv, buv);
            }
        }

        if (pre) {
            sts_b_g1_half(stn, tid, 1, sgv, suv, bgv, buv);
            CP_WAIT0();
        }
        __syncthreads();
    }

    // Epilogue: h = silu(gate) * up -> fp16 g_h
#pragma unroll
    for (int mi = 0; mi < 2; mi++)
#pragma unroll
        for (int n = 0; n < 4; n++) {
            int row = t0 + wm * 32 + mi * 16 + (l >> 2);
            int col = i0 + wn * 32 + n * 8 + ((l & 3) << 1);
            {
                float g0 = cg[mi][n][0], g1 = cg[mi][n][1];
                float h0 = g0 * cu[mi][n][0] / (1.0f + __expf(-g0));
                float h1 = g1 * cu[mi][n][1] / (1.0f + __expf(-g1));
                __half2 hv = __floats2half2_rn(h0, h1);
                *(uint32_t*)(&g_h[(size_t)row * I_DIM + col]) = *(uint32_t*)&hv;
            }
            {
                float g0 = cg[mi][n][2], g1 = cg[mi][n][3];
                float h0 = g0 * cu[mi][n][2] / (1.0f + __expf(-g0));
                float h1 = g1 * cu[mi][n][3] / (1.0f + __expf(-g1));
                __half2 hv = __floats2half2_rn(h0, h1);
                *(uint32_t*)(&g_h[(size_t)(row + 8) * I_DIM + col]) = *(uint32_t*)&hv;
            }
        }
}

// ---------------------------------------------------------------------------
// GEMM2 staging (tile 128x64, BK=64) — unchanged from R11
// ---------------------------------------------------------------------------
__device__ __forceinline__ void cp_a_g2(uint32_t sA, int t0, int k0, int tid) {
#pragma unroll
    for (int j = 0; j < 4; j++) {
        int idx = tid + j * 256;
        int r = idx >> 3, c = idx & 7;
        cp16(sA + r * G2_PITCH + c * 16, g_h + (size_t)(t0 + r) * I_DIM + k0 + c * 8);
    }
    CP_COMMIT();
}

__device__ __forceinline__ void ldg_b_g2(const float* __restrict__ wd,
                                         int h0, int k0, int tid, float4* b4) {
#pragma unroll
    for (int j = 0; j < 4; j++) {
        int idx = tid + j * 256;
        int r = idx >> 4, c4 = idx & 15;
        b4[j] = *(const float4*)(wd + (size_t)(k0 + r) * H_DIM + h0 + c4 * 4);
    }
}

__device__ __forceinline__ void sts_b_g2(char* st, int tid, float s, const float4* b4) {
#pragma unroll
    for (int j = 0; j < 4; j++) {
        int idx = tid + j * 256;
        int r = idx >> 4, c4 = idx & 15;
        __half2 h0 = __floats2half2_rn(b4[j].x * s, b4[j].y * s);
        __half2 h1 = __floats2half2_rn(b4[j].z * s, b4[j].w * s);
        uint2 w;
        w.x = *(uint32_t*)&h0; w.y = *(uint32_t*)&h1;
        *(uint2*)(st + G2_A_BYTES + r * G2_PITCH + c4 * 8) = w;
    }
}

__global__ __launch_bounds__(256, 2) void gemm2_kernel(
    const float* __restrict__ wd, const float* __restrict__ sd,
    float* __restrict__ out) {
    extern __shared__ __align__(128) char sm2[];
    const int tid = threadIdx.x, wid = tid >> 5, l = tid & 31;
    const int wm = wid & 3, wn = wid >> 2;
    const int t0 = blockIdx.x * 128, h0 = blockIdx.y * 64;
    const int hb = h0 >> 7;
    const uint32_t sbase = smem_u32(sm2);

    float c[2][4][4];
#pragma unroll
    for (int a = 0; a < 2; a++)
#pragma unroll
        for (int b = 0; b < 4; b++)
#pragma unroll
            for (int d = 0; d < 4; d++) c[a][b][d] = 0.f;

    float4 b4[4];
    cp_a_g2(sbase, t0, 0, tid);
    ldg_b_g2(wd, h0, 0, tid, b4);
    sts_b_g2(sm2, tid, __ldg(sd + hb), b4);
    CP_WAIT0();
    __syncthreads();

    for (int it = 0; it < NK2; it++) {
        float sv = 0.f;
        if (it + 1 < NK2) {
            cp_a_g2(sbase + ((it + 1) & 1) * G2_STAGE, t0, (it + 1) * 64, tid);
            ldg_b_g2(wd, h0, (it + 1) * 64, tid, b4);
            sv = __ldg(sd + ((it + 1) >> 1) * (H_DIM / 128) + hb);
        }

        const uint32_t sA = sbase + (it & 1) * G2_STAGE;
        const uint32_t sB = sA + G2_A_BYTES;
#pragma unroll
        for (int kk = 0; kk < 64; kk += 16) {
            uint32_t a2[2][4];
#pragma unroll
            for (int mi = 0; mi < 2; mi++)
                ldsm_x4(a2[mi], sA + (wm * 32 + mi * 16 + (l & 15)) * G2_PITCH +
                                   (kk + ((l >> 4) << 3)) * 2);
            uint32_t bf[4][2];
#pragma unroll
            for (int p = 0; p < 2; p++) {
                int t = l >> 3, rr = l & 7;
                uint32_t baddr = sB + (kk + (t & 1) * 8 + rr) * G2_PITCH +
                                 (wn * 32 + p * 16 + (t >> 1) * 8) * 2;
                uint32_t r4[4];
                ldsm_x4_t(r4, baddr);
                bf[p * 2][0] = r4[0]; bf[p * 2][1] = r4[1];
                bf[p * 2 + 1][0] = r4[2]; bf[p * 2 + 1][1] = r4[3];
            }
#pragma unroll
            for (int mi = 0; mi < 2; mi++)
#pragma unroll
                for (int n = 0; n < 4; n++)
                    mma16816(c[mi][n], a2[mi], bf[n]);
        }

        if (it + 1 < NK2) {
            sts_b_g2(sm2 + ((it + 1) & 1) * G2_STAGE, tid, sv, b4);
            CP_WAIT0();
        }
        __syncthreads();
    }

#pragma unroll
    for (int mi = 0; mi < 2; mi++)
#pragma unroll
        for (int n = 0; n < 4; n++) {
            int row = t0 + wm * 32 + mi * 16 + (l >> 2);
            int col = h0 + wn * 32 + n * 8 + ((l & 3) << 1);
            float2 v0 = make_float2(c[mi][n][0], c[mi][n][1]);
            float2 v1 = make_float2(c[mi][n][2], c[mi][n][3]);
            *(float2*)(out + (size_t)row * H_DIM + col) = v0;
            *(float2*)(out + (size_t)(row + 8) * H_DIM + col) = v1;
        }
}

// ---------------------------------------------------------------------------
// Launch
// ---------------------------------------------------------------------------
extern "C" void kernel_launch(void* const* d_in, const int* in_sizes, int n_in,
                              void* d_out, int out_size) {
    const float* x  = (const float*)d_in[0];
    const float* wg = (const float*)d_in[1];
    const float* wu = (const float*)d_in[2];
    const float* wd = (const float*)d_in[3];
    const float* sg = (const float*)d_in[4];
    const float* su = (const float*)d_in[5];
    const float* sd = (const float*)d_in[6];
    float* out = (float*)d_out;
    (void)in_sizes; (void)n_in; (void)out_size;

    cudaFuncSetAttribute(gemm1_kernel, cudaFuncAttributeMaxDynamicSharedMemorySize,
                         G1_SMEM);
    cudaFuncSetAttribute(gemm2_kernel, cudaFuncAttributeMaxDynamicSharedMemorySize,
                         G2_SMEM);

    cvt_x_kernel<<<(T_DIM * H_DIM / 4) / 256, 256>>>(x);
    // T-tiles fastest (blockIdx.x) so concurrent CTAs dedup weight reads in L2
    gemm1_kernel<<<dim3(T_DIM / 128, I_DIM / 64), 256, G1_SMEM>>>(wg, wu, sg, su);
    gemm2_kernel<<<dim3(T_DIM / 128, H_DIM / 64), 256, G2_SMEM>>>(wd, sd, out);
}